// round 2
// baseline (speedup 1.0000x reference)
#include <cuda_runtime.h>
#include <cuda_bf16.h>
#include <math.h>

// Problem constants
#define BATCH 2
#define SEQ   2048
#define CDIM  2048
#define NHEAD 16
#define NKV   4
#define HEADD 128
#define GROUP (NHEAD / NKV)      // 4
#define ROWS  (BATCH * SEQ)      // 4096
#define KVC   (NKV * HEADD)      // 512

// Scratch (device globals; allocation is forbidden)
__device__ __align__(128) float g_Q[(size_t)ROWS * CDIM];
__device__ __align__(128) float g_K[(size_t)ROWS * KVC];
__device__ __align__(128) float g_V[(size_t)ROWS * KVC];
__device__ __align__(128) float g_Y[(size_t)ROWS * CDIM];

// ---------------------------------------------------------------------------
// Tiled fp32 GEMM: C[M,N] = A[M,K] @ B[K,N], all row-major.
// 128x128 block tile, BK=16, 256 threads, 8x8 per thread, float4 everywhere.
// Requires M%128==0, N%128==0, K%16==0 (true for all our shapes).
// ---------------------------------------------------------------------------
__global__ __launch_bounds__(256, 2)
void gemm_kernel(const float* __restrict__ A, const float* __restrict__ B,
                 float* __restrict__ C, int M, int N, int Kdim)
{
    __shared__ float As[16][128];   // stored transposed: As[k][m]
    __shared__ float Bs[16][128];   // Bs[k][n]

    const int bm = blockIdx.y * 128;
    const int bn = blockIdx.x * 128;
    const int tid = threadIdx.x;
    const int tr = (tid >> 4) * 8;    // row offset within tile (0..120)
    const int tc = (tid & 15) * 8;    // col offset within tile

    float acc[8][8];
#pragma unroll
    for (int i = 0; i < 8; i++)
#pragma unroll
        for (int j = 0; j < 8; j++) acc[i][j] = 0.0f;

    for (int k0 = 0; k0 < Kdim; k0 += 16) {
        // Load A tile (128 rows x 16 cols) -> As transposed
#pragma unroll
        for (int it = 0; it < 2; it++) {
            int idx = tid * 2 + it;            // 0..511
            int r  = idx >> 2;                 // 0..127
            int kq = (idx & 3) * 4;            // 0,4,8,12
            float4 a = *(const float4*)(A + (size_t)(bm + r) * Kdim + k0 + kq);
            As[kq + 0][r] = a.x;
            As[kq + 1][r] = a.y;
            As[kq + 2][r] = a.z;
            As[kq + 3][r] = a.w;
        }
        // Load B tile (16 rows x 128 cols)
#pragma unroll
        for (int it = 0; it < 2; it++) {
            int idx = tid * 2 + it;            // 0..511
            int rb = idx >> 5;                 // 0..15
            int cb = (idx & 31) * 4;           // 0..124
            *(float4*)(&Bs[rb][cb]) =
                *(const float4*)(B + (size_t)(k0 + rb) * N + bn + cb);
        }
        __syncthreads();

#pragma unroll
        for (int kk = 0; kk < 16; kk++) {
            float ra[8], rb[8];
            *(float4*)(ra)     = *(const float4*)(&As[kk][tr]);
            *(float4*)(ra + 4) = *(const float4*)(&As[kk][tr + 4]);
            *(float4*)(rb)     = *(const float4*)(&Bs[kk][tc]);
            *(float4*)(rb + 4) = *(const float4*)(&Bs[kk][tc + 4]);
#pragma unroll
            for (int i = 0; i < 8; i++)
#pragma unroll
                for (int j = 0; j < 8; j++)
                    acc[i][j] += ra[i] * rb[j];
        }
        __syncthreads();
    }

    // Store
#pragma unroll
    for (int i = 0; i < 8; i++) {
        float* crow = C + (size_t)(bm + tr + i) * N + bn + tc;
        float4 v0 = make_float4(acc[i][0], acc[i][1], acc[i][2], acc[i][3]);
        float4 v1 = make_float4(acc[i][4], acc[i][5], acc[i][6], acc[i][7]);
        *(float4*)(crow)     = v0;
        *(float4*)(crow + 4) = v1;
    }
}

// ---------------------------------------------------------------------------
// Flash attention (fp32 SIMT), causal, GQA.
// Grid: (T/64, NHEAD, BATCH). Block: 256 threads (16x16 logical).
// Per block: 64 queries x D=128. KV tiles of 64. Online softmax.
// Output written to Y in (B,T,H,D) layout (== (ROWS, CDIM) row-major).
// ---------------------------------------------------------------------------
#define BQ 64
#define BKV 64
#define QROW 132       // padded row stride (floats); 132*4 % 16 == 0
#define PROW 65

#define FLASH_SMEM_BYTES ((3 * BQ * QROW + BQ * PROW) * 4)

__global__ __launch_bounds__(256, 1)
void flash_kernel(const float* __restrict__ Q, const float* __restrict__ K,
                  const float* __restrict__ V, float* __restrict__ Y)
{
    extern __shared__ float sm[];
    float* Qs = sm;                    // BQ x QROW
    float* Ks = Qs + BQ * QROW;        // BKV x QROW
    float* Vs = Ks + BQ * QROW;        // BKV x QROW
    float* Ps = Vs + BQ * QROW;        // BQ x PROW

    const int q0  = blockIdx.x * BQ;
    const int h   = blockIdx.y;
    const int b   = blockIdx.z;
    const int kvh = h / GROUP;
    const int tid = threadIdx.x;
    const int ty  = tid >> 4;          // 0..15
    const int tx  = tid & 15;          // 0..15
    const float scale = 0.08838834764831845f;  // 1/sqrt(128)

    // Load Q tile: rows q0..q0+63 (within batch b), cols h*128..+127
    const float* Qbase = Q + ((size_t)(b * SEQ + q0)) * CDIM + h * HEADD;
#pragma unroll
    for (int it = 0; it < 8; it++) {
        int idx = tid + it * 256;      // 0..2047 float4 items
        int r  = idx >> 5;             // 0..63
        int c4 = (idx & 31) * 4;       // 0..124
        *(float4*)(Qs + r * QROW + c4) =
            *(const float4*)(Qbase + (size_t)r * CDIM + c4);
    }

    float m_i[4], l_i[4], O[4][8];
#pragma unroll
    for (int i = 0; i < 4; i++) {
        m_i[i] = -1e30f;
        l_i[i] = 0.0f;
#pragma unroll
        for (int j = 0; j < 8; j++) O[i][j] = 0.0f;
    }

    const int ntiles = q0 / BKV + 1;
    for (int t = 0; t < ntiles; t++) {
        const int k0 = t * BKV;
        __syncthreads();   // protect Ks/Vs/Ps from previous iteration

        const float* Kbase = K + ((size_t)(b * SEQ + k0)) * KVC + kvh * HEADD;
        const float* Vbase = V + ((size_t)(b * SEQ + k0)) * KVC + kvh * HEADD;
#pragma unroll
        for (int it = 0; it < 8; it++) {
            int idx = tid + it * 256;
            int r  = idx >> 5;
            int c4 = (idx & 31) * 4;
            *(float4*)(Ks + r * QROW + c4) =
                *(const float4*)(Kbase + (size_t)r * KVC + c4);
            *(float4*)(Vs + r * QROW + c4) =
                *(const float4*)(Vbase + (size_t)r * KVC + c4);
        }
        __syncthreads();

        // S = Q_tile @ K_tile^T : each thread 4x4
        float s[4][4];
#pragma unroll
        for (int i = 0; i < 4; i++)
#pragma unroll
            for (int j = 0; j < 4; j++) s[i][j] = 0.0f;

        for (int d = 0; d < HEADD; d += 4) {
            float4 qv[4], kv[4];
#pragma unroll
            for (int i = 0; i < 4; i++)
                qv[i] = *(const float4*)(Qs + (ty * 4 + i) * QROW + d);
#pragma unroll
            for (int j = 0; j < 4; j++)
                kv[j] = *(const float4*)(Ks + (tx * 4 + j) * QROW + d);
#pragma unroll
            for (int i = 0; i < 4; i++)
#pragma unroll
                for (int j = 0; j < 4; j++) {
                    s[i][j] += qv[i].x * kv[j].x;
                    s[i][j] += qv[i].y * kv[j].y;
                    s[i][j] += qv[i].z * kv[j].z;
                    s[i][j] += qv[i].w * kv[j].w;
                }
        }

        // Online softmax update (rows owned by ty, replicated across tx group)
        const bool diag = (k0 == q0);
#pragma unroll
        for (int i = 0; i < 4; i++) {
            const int qg = q0 + ty * 4 + i;
            float sv[4];
            float mt = -1e30f;
#pragma unroll
            for (int j = 0; j < 4; j++) {
                float x = s[i][j] * scale;
                if (diag && (k0 + tx * 4 + j > qg)) x = -1e30f;
                sv[j] = x;
                mt = fmaxf(mt, x);
            }
#pragma unroll
            for (int o = 8; o >= 1; o >>= 1)
                mt = fmaxf(mt, __shfl_xor_sync(0xffffffffu, mt, o));
            const float mnew = fmaxf(m_i[i], mt);
            const float corr = __expf(m_i[i] - mnew);
            float psum = 0.0f;
#pragma unroll
            for (int j = 0; j < 4; j++) {
                float p = __expf(sv[j] - mnew);
                Ps[(ty * 4 + i) * PROW + tx * 4 + j] = p;
                psum += p;
            }
#pragma unroll
            for (int o = 8; o >= 1; o >>= 1)
                psum += __shfl_xor_sync(0xffffffffu, psum, o);
            l_i[i] = l_i[i] * corr + psum;
            m_i[i] = mnew;
#pragma unroll
            for (int j = 0; j < 8; j++) O[i][j] *= corr;
        }
        __syncthreads();   // Ps fully written before PV

        // O += P @ V : thread owns rows ty*4.., cols tx*8..
#pragma unroll 2
        for (int kj = 0; kj < BKV; kj++) {
            float4 v0 = *(const float4*)(Vs + kj * QROW + tx * 8);
            float4 v1 = *(const float4*)(Vs + kj * QROW + tx * 8 + 4);
#pragma unroll
            for (int i = 0; i < 4; i++) {
                float p = Ps[(ty * 4 + i) * PROW + kj];
                O[i][0] += p * v0.x;
                O[i][1] += p * v0.y;
                O[i][2] += p * v0.z;
                O[i][3] += p * v0.w;
                O[i][4] += p * v1.x;
                O[i][5] += p * v1.y;
                O[i][6] += p * v1.z;
                O[i][7] += p * v1.w;
            }
        }
    }

    // Normalize + write Y in (B,T,H,D) layout
    float* Ybase = Y + ((size_t)(b * SEQ + q0)) * CDIM + h * HEADD;
#pragma unroll
    for (int i = 0; i < 4; i++) {
        const float inv = 1.0f / l_i[i];
        float* yrow = Ybase + (size_t)(ty * 4 + i) * CDIM + tx * 8;
        float4 v0 = make_float4(O[i][0] * inv, O[i][1] * inv,
                                O[i][2] * inv, O[i][3] * inv);
        float4 v1 = make_float4(O[i][4] * inv, O[i][5] * inv,
                                O[i][6] * inv, O[i][7] * inv);
        *(float4*)(yrow)     = v0;
        *(float4*)(yrow + 4) = v1;
    }
}

// ---------------------------------------------------------------------------
extern "C" void kernel_launch(void* const* d_in, const int* in_sizes, int n_in,
                              void* d_out, int out_size)
{
    const float* x  = (const float*)d_in[0];
    const float* Wq = (const float*)d_in[1];
    const float* Wk = (const float*)d_in[2];
    const float* Wv = (const float*)d_in[3];
    const float* Wo = (const float*)d_in[4];
    float* out = (float*)d_out;

    float *Qb, *Kb, *Vb, *Yb;
    cudaGetSymbolAddress((void**)&Qb, g_Q);
    cudaGetSymbolAddress((void**)&Kb, g_K);
    cudaGetSymbolAddress((void**)&Vb, g_V);
    cudaGetSymbolAddress((void**)&Yb, g_Y);

    // QKV projections
    gemm_kernel<<<dim3(CDIM / 128, ROWS / 128), 256>>>(x, Wq, Qb, ROWS, CDIM, CDIM);
    gemm_kernel<<<dim3(KVC  / 128, ROWS / 128), 256>>>(x, Wk, Kb, ROWS, KVC,  CDIM);
    gemm_kernel<<<dim3(KVC  / 128, ROWS / 128), 256>>>(x, Wv, Vb, ROWS, KVC,  CDIM);

    // Flash attention
    cudaFuncSetAttribute(flash_kernel,
                         cudaFuncAttributeMaxDynamicSharedMemorySize,
                         FLASH_SMEM_BYTES);
    flash_kernel<<<dim3(SEQ / BQ, NHEAD, BATCH), 256, FLASH_SMEM_BYTES>>>(
        Qb, Kb, Vb, Yb);

    // Output projection
    gemm_kernel<<<dim3(CDIM / 128, ROWS / 128), 256>>>(Yb, Wo, out, ROWS, CDIM, CDIM);
}

// round 4
// speedup vs baseline: 3.7811x; 3.7811x over previous
#include <cuda_runtime.h>
#include <cuda_bf16.h>
#include <math.h>
#include <stdint.h>

// Problem constants
#define BATCH 2
#define SEQ   2048
#define CDIM  2048
#define NHEAD 16
#define NKV   4
#define HEADD 128
#define GROUP (NHEAD / NKV)      // 4
#define ROWS  (BATCH * SEQ)      // 4096
#define KVC   (NKV * HEADD)      // 512

// Scratch (device globals; allocation is forbidden)
__device__ __align__(128) float g_Q[(size_t)ROWS * CDIM];
__device__ __align__(128) float g_K[(size_t)ROWS * KVC];
__device__ __align__(128) float g_V[(size_t)ROWS * KVC];
__device__ __align__(128) float g_Y[(size_t)ROWS * CDIM];

__device__ __forceinline__ float to_tf32(float x) {
    float r;
    asm("cvt.rna.tf32.f32 %0, %1;" : "=f"(r) : "f"(x));
    return r;
}
__device__ __forceinline__ uint32_t U(float x) { return __float_as_uint(x); }

#define MMA_TF32(D, a0, a1, a2, a3, b0, b1)                                   \
    asm volatile(                                                             \
        "mma.sync.aligned.m16n8k8.row.col.f32.tf32.tf32.f32 "                 \
        "{%0,%1,%2,%3}, {%4,%5,%6,%7}, {%8,%9}, {%0,%1,%2,%3};"               \
        : "+f"(D[0]), "+f"(D[1]), "+f"(D[2]), "+f"(D[3])                      \
        : "r"(a0), "r"(a1), "r"(a2), "r"(a3), "r"(b0), "r"(b1))

// ---------------------------------------------------------------------------
// tf32 tensor-core GEMM: C[M,N] = A[M,K] @ B[K,N], row-major.
// 128x128 block tile, BK=32, 256 threads (8 warps, 32x64 warp tiles).
// Smem strides chosen for conflict-free HMMA fragment loads:
//   As stride 36  (36 mod 32 == 4  -> bank = 4g+t, injective)
//   Bs stride 136 (136 mod 32 == 8 -> bank = 8t+g, injective)
// ---------------------------------------------------------------------------
#define AS_STR 36
#define BS_STR 136

__global__ __launch_bounds__(256, 2)
void gemm_tf32(const float* __restrict__ A, const float* __restrict__ B,
               float* __restrict__ C, int M, int N, int Kdim)
{
    __shared__ float As[128 * AS_STR];   // [row][k]
    __shared__ float Bs[32 * BS_STR];    // [k][col]

    const int bm = blockIdx.y * 128;
    const int bn = blockIdx.x * 128;
    const int tid  = threadIdx.x;
    const int wid  = tid >> 5;
    const int lane = tid & 31;
    const int g = lane >> 2;   // 0..7
    const int t = lane & 3;    // 0..3
    const int wr = (wid & 3) * 32;   // warp row base (0..96)
    const int wc = (wid >> 2) * 64;  // warp col base (0 or 64)

    float acc[2][8][4];
#pragma unroll
    for (int mt = 0; mt < 2; mt++)
#pragma unroll
        for (int nt = 0; nt < 8; nt++)
#pragma unroll
            for (int e = 0; e < 4; e++) acc[mt][nt][e] = 0.0f;

    for (int k0 = 0; k0 < Kdim; k0 += 32) {
        // Load A tile (128x32) and B tile (32x128), rounding to tf32.
#pragma unroll
        for (int i = 0; i < 4; i++) {
            int idx = tid + i * 256;             // 0..1023
            int ra = idx >> 3, ca = (idx & 7) * 4;
            float4 av = *(const float4*)(A + (size_t)(bm + ra) * Kdim + k0 + ca);
            float* dst = &As[ra * AS_STR + ca];
            dst[0] = to_tf32(av.x); dst[1] = to_tf32(av.y);
            dst[2] = to_tf32(av.z); dst[3] = to_tf32(av.w);

            int rb = idx >> 5, cb = (idx & 31) * 4;
            float4 bv = *(const float4*)(B + (size_t)(k0 + rb) * N + bn + cb);
            float* dstb = &Bs[rb * BS_STR + cb];
            dstb[0] = to_tf32(bv.x); dstb[1] = to_tf32(bv.y);
            dstb[2] = to_tf32(bv.z); dstb[3] = to_tf32(bv.w);
        }
        __syncthreads();

#pragma unroll
        for (int ks = 0; ks < 4; ks++) {
            const int kk = ks * 8;
            uint32_t a[2][4];
#pragma unroll
            for (int mt = 0; mt < 2; mt++) {
                int rb = wr + mt * 16;
                a[mt][0] = U(As[(rb + g)     * AS_STR + kk + t]);
                a[mt][1] = U(As[(rb + 8 + g) * AS_STR + kk + t]);
                a[mt][2] = U(As[(rb + g)     * AS_STR + kk + t + 4]);
                a[mt][3] = U(As[(rb + 8 + g) * AS_STR + kk + t + 4]);
            }
            uint32_t bf[8][2];
#pragma unroll
            for (int nt = 0; nt < 8; nt++) {
                int c = wc + nt * 8 + g;
                bf[nt][0] = U(Bs[(kk + t)     * BS_STR + c]);
                bf[nt][1] = U(Bs[(kk + t + 4) * BS_STR + c]);
            }
#pragma unroll
            for (int mt = 0; mt < 2; mt++)
#pragma unroll
                for (int nt = 0; nt < 8; nt++)
                    MMA_TF32(acc[mt][nt], a[mt][0], a[mt][1], a[mt][2], a[mt][3],
                             bf[nt][0], bf[nt][1]);
        }
        __syncthreads();
    }

    // Epilogue: c0,c1 -> row g, cols 2t,2t+1 ; c2,c3 -> row g+8.
#pragma unroll
    for (int mt = 0; mt < 2; mt++) {
        int r = bm + wr + mt * 16 + g;
#pragma unroll
        for (int nt = 0; nt < 8; nt++) {
            int c = bn + wc + nt * 8 + 2 * t;
            *(float2*)(C + (size_t)r * N + c) =
                make_float2(acc[mt][nt][0], acc[mt][nt][1]);
            *(float2*)(C + (size_t)(r + 8) * N + c) =
                make_float2(acc[mt][nt][2], acc[mt][nt][3]);
        }
    }
}

// ---------------------------------------------------------------------------
// Flash attention on tf32 HMMA. Causal, GQA.
// Block: 256 threads (8 warps). BQ=128 queries/block, warp owns 16 rows.
// BKV=64 keys per tile. D=128. Online softmax in accumulator layout.
// Smem strides: Qs/Ks/Ps ≡ 4 (mod 32)  [bank = 4g+t injective]
//               Vs       ≡ 8 (mod 32)  [bank = 8t+g injective]
// ---------------------------------------------------------------------------
#define BQ 128
#define BKV 64
#define QS_STR 132
#define KS_STR 132
#define VS_STR 136
#define PS_STR 68

#define FLASH_SMEM_FLOATS (BQ * QS_STR + BKV * KS_STR + BKV * VS_STR + BQ * PS_STR)
#define FLASH_SMEM_BYTES  (FLASH_SMEM_FLOATS * 4)

__global__ __launch_bounds__(256, 1)
void flash_tf32(const float* __restrict__ Q, const float* __restrict__ K,
                const float* __restrict__ V, float* __restrict__ Y)
{
    extern __shared__ float sm[];
    float* Qs = sm;                          // BQ  x QS_STR
    float* Ks = Qs + BQ * QS_STR;            // BKV x KS_STR
    float* Vs = Ks + BKV * KS_STR;           // BKV x VS_STR
    float* Ps = Vs + BKV * VS_STR;           // BQ  x PS_STR

    const int q0  = blockIdx.x * BQ;
    const int h   = blockIdx.y;
    const int b   = blockIdx.z;
    const int kvh = h / GROUP;
    const int tid  = threadIdx.x;
    const int wid  = tid >> 5;
    const int lane = tid & 31;
    const int g = lane >> 2;
    const int t = lane & 3;
    const int wr = wid * 16;                 // warp's row base within tile
    const float scale = 0.08838834764831845f;  // 1/sqrt(128)

    // Load Q tile (pre-scaled, tf32-rounded)
    const float* Qbase = Q + (size_t)(b * SEQ + q0) * CDIM + h * HEADD;
#pragma unroll
    for (int i = 0; i < 16; i++) {
        int idx = tid + i * 256;             // 4096 float4 slots
        int r = idx >> 5, c4 = (idx & 31) * 4;
        float4 v = *(const float4*)(Qbase + (size_t)r * CDIM + c4);
        float* dst = &Qs[r * QS_STR + c4];
        dst[0] = to_tf32(v.x * scale); dst[1] = to_tf32(v.y * scale);
        dst[2] = to_tf32(v.z * scale); dst[3] = to_tf32(v.w * scale);
    }

    float oa[16][4];
#pragma unroll
    for (int nt = 0; nt < 16; nt++)
#pragma unroll
        for (int e = 0; e < 4; e++) oa[nt][e] = 0.0f;
    float m0 = -1e30f, m1 = -1e30f, l0 = 0.0f, l1 = 0.0f;

    const int qrow0 = q0 + wr + g;
    const int qrow1 = qrow0 + 8;
    const int ntiles = q0 / BKV + 2;         // (q0 + BQ) / BKV

    for (int tt = 0; tt < ntiles; tt++) {
        const int k0 = tt * BKV;
        __syncthreads();                     // prev iter done with Ks/Vs

        const float* Kbase = K + (size_t)(b * SEQ + k0) * KVC + kvh * HEADD;
        const float* Vbase = V + (size_t)(b * SEQ + k0) * KVC + kvh * HEADD;
#pragma unroll
        for (int i = 0; i < 8; i++) {
            int idx = tid + i * 256;         // 2048 float4 slots
            int r = idx >> 5, c4 = (idx & 31) * 4;
            float4 kv = *(const float4*)(Kbase + (size_t)r * KVC + c4);
            float* dk = &Ks[r * KS_STR + c4];
            dk[0] = to_tf32(kv.x); dk[1] = to_tf32(kv.y);
            dk[2] = to_tf32(kv.z); dk[3] = to_tf32(kv.w);
            float4 vv = *(const float4*)(Vbase + (size_t)r * KVC + c4);
            float* dv = &Vs[r * VS_STR + c4];
            dv[0] = to_tf32(vv.x); dv[1] = to_tf32(vv.y);
            dv[2] = to_tf32(vv.z); dv[3] = to_tf32(vv.w);
        }
        __syncthreads();

        // ---- S = Q @ K^T (warp: 16 x 64) ----
        float sa[8][4];
#pragma unroll
        for (int j = 0; j < 8; j++)
#pragma unroll
            for (int e = 0; e < 4; e++) sa[j][e] = 0.0f;

#pragma unroll
        for (int ks = 0; ks < 16; ks++) {
            const int kk = ks * 8;
            uint32_t a0 = U(Qs[(wr + g)     * QS_STR + kk + t]);
            uint32_t a1 = U(Qs[(wr + 8 + g) * QS_STR + kk + t]);
            uint32_t a2 = U(Qs[(wr + g)     * QS_STR + kk + t + 4]);
            uint32_t a3 = U(Qs[(wr + 8 + g) * QS_STR + kk + t + 4]);
#pragma unroll
            for (int j = 0; j < 8; j++) {
                uint32_t b0 = U(Ks[(8 * j + g) * KS_STR + kk + t]);
                uint32_t b1 = U(Ks[(8 * j + g) * KS_STR + kk + t + 4]);
                MMA_TF32(sa[j], a0, a1, a2, a3, b0, b1);
            }
        }

        // ---- online softmax (accumulator layout: rows g, g+8) ----
        float ml0 = -1e30f, ml1 = -1e30f;
#pragma unroll
        for (int j = 0; j < 8; j++)
#pragma unroll
            for (int e = 0; e < 2; e++) {
                int key = k0 + 8 * j + 2 * t + e;
                if (key > qrow0) sa[j][e]     = -1e30f;
                if (key > qrow1) sa[j][2 + e] = -1e30f;
                ml0 = fmaxf(ml0, sa[j][e]);
                ml1 = fmaxf(ml1, sa[j][2 + e]);
            }
        ml0 = fmaxf(ml0, __shfl_xor_sync(0xffffffffu, ml0, 1));
        ml0 = fmaxf(ml0, __shfl_xor_sync(0xffffffffu, ml0, 2));
        ml1 = fmaxf(ml1, __shfl_xor_sync(0xffffffffu, ml1, 1));
        ml1 = fmaxf(ml1, __shfl_xor_sync(0xffffffffu, ml1, 2));

        float mn0 = fmaxf(m0, ml0), mn1 = fmaxf(m1, ml1);
        float corr0 = __expf(m0 - mn0), corr1 = __expf(m1 - mn1);
        m0 = mn0; m1 = mn1;

        float s0 = 0.0f, s1 = 0.0f;
#pragma unroll
        for (int j = 0; j < 8; j++)
#pragma unroll
            for (int e = 0; e < 2; e++) {
                int col = 8 * j + 2 * t + e;
                float p0 = __expf(sa[j][e] - mn0);
                float p1 = __expf(sa[j][2 + e] - mn1);
                Ps[(wr + g)     * PS_STR + col] = to_tf32(p0);
                Ps[(wr + 8 + g) * PS_STR + col] = to_tf32(p1);
                s0 += p0; s1 += p1;
            }
        s0 += __shfl_xor_sync(0xffffffffu, s0, 1);
        s0 += __shfl_xor_sync(0xffffffffu, s0, 2);
        s1 += __shfl_xor_sync(0xffffffffu, s1, 1);
        s1 += __shfl_xor_sync(0xffffffffu, s1, 2);
        l0 = l0 * corr0 + s0;
        l1 = l1 * corr1 + s1;

#pragma unroll
        for (int nt = 0; nt < 16; nt++) {
            oa[nt][0] *= corr0; oa[nt][1] *= corr0;
            oa[nt][2] *= corr1; oa[nt][3] *= corr1;
        }
        __syncwarp();

        // ---- O += P @ V (warp: 16 x 128) ----
#pragma unroll
        for (int ks = 0; ks < 8; ks++) {
            const int kk = ks * 8;
            uint32_t a0 = U(Ps[(wr + g)     * PS_STR + kk + t]);
            uint32_t a1 = U(Ps[(wr + 8 + g) * PS_STR + kk + t]);
            uint32_t a2 = U(Ps[(wr + g)     * PS_STR + kk + t + 4]);
            uint32_t a3 = U(Ps[(wr + 8 + g) * PS_STR + kk + t + 4]);
#pragma unroll
            for (int nt = 0; nt < 16; nt++) {
                uint32_t b0 = U(Vs[(kk + t)     * VS_STR + 8 * nt + g]);
                uint32_t b1 = U(Vs[(kk + t + 4) * VS_STR + 8 * nt + g]);
                MMA_TF32(oa[nt], a0, a1, a2, a3, b0, b1);
            }
        }
    }

    // ---- normalize + write Y in (B,T,H,D) layout ----
    const float inv0 = 1.0f / l0, inv1 = 1.0f / l1;
    float* Ybase = Y + (size_t)(b * SEQ + q0 + wr) * CDIM + h * HEADD;
#pragma unroll
    for (int nt = 0; nt < 16; nt++) {
        int col = 8 * nt + 2 * t;
        *(float2*)(Ybase + (size_t)g * CDIM + col) =
            make_float2(oa[nt][0] * inv0, oa[nt][1] * inv0);
        *(float2*)(Ybase + (size_t)(g + 8) * CDIM + col) =
            make_float2(oa[nt][2] * inv1, oa[nt][3] * inv1);
    }
}

// ---------------------------------------------------------------------------
extern "C" void kernel_launch(void* const* d_in, const int* in_sizes, int n_in,
                              void* d_out, int out_size)
{
    const float* x  = (const float*)d_in[0];
    const float* Wq = (const float*)d_in[1];
    const float* Wk = (const float*)d_in[2];
    const float* Wv = (const float*)d_in[3];
    const float* Wo = (const float*)d_in[4];
    float* out = (float*)d_out;

    float *Qb, *Kb, *Vb, *Yb;
    cudaGetSymbolAddress((void**)&Qb, g_Q);
    cudaGetSymbolAddress((void**)&Kb, g_K);
    cudaGetSymbolAddress((void**)&Vb, g_V);
    cudaGetSymbolAddress((void**)&Yb, g_Y);

    // QKV projections (tf32 tensor cores)
    gemm_tf32<<<dim3(CDIM / 128, ROWS / 128), 256>>>(x, Wq, Qb, ROWS, CDIM, CDIM);
    gemm_tf32<<<dim3(KVC  / 128, ROWS / 128), 256>>>(x, Wk, Kb, ROWS, KVC,  CDIM);
    gemm_tf32<<<dim3(KVC  / 128, ROWS / 128), 256>>>(x, Wv, Vb, ROWS, KVC,  CDIM);

    // Flash attention (tf32 tensor cores)
    cudaFuncSetAttribute(flash_tf32,
                         cudaFuncAttributeMaxDynamicSharedMemorySize,
                         FLASH_SMEM_BYTES);
    flash_tf32<<<dim3(SEQ / BQ, NHEAD, BATCH), 256, FLASH_SMEM_BYTES>>>(
        Qb, Kb, Vb, Yb);

    // Output projection
    gemm_tf32<<<dim3(CDIM / 128, ROWS / 128), 256>>>(Yb, Wo, out, ROWS, CDIM, CDIM);
}

// round 6
// speedup vs baseline: 6.0981x; 1.6128x over previous
#include <cuda_runtime.h>
#include <cuda_fp16.h>
#include <math.h>
#include <stdint.h>

// Problem constants
#define BATCH 2
#define SEQ   2048
#define CDIM  2048
#define NHEAD 16
#define NKV   4
#define HEADD 128
#define GROUP (NHEAD / NKV)      // 4
#define ROWS  (BATCH * SEQ)      // 4096
#define KVC   (NKV * HEADD)      // 512

// Scratch (device globals; allocation is forbidden)
__device__ __align__(128) __half g_xh [(size_t)ROWS * CDIM];
__device__ __align__(128) __half g_Qh [(size_t)ROWS * CDIM];
__device__ __align__(128) __half g_Kh [(size_t)ROWS * KVC];
__device__ __align__(128) __half g_Vt [(size_t)KVC * ROWS];   // transposed V
__device__ __align__(128) __half g_Yh [(size_t)ROWS * CDIM];
__device__ __align__(128) __half g_WqT[(size_t)CDIM * CDIM];
__device__ __align__(128) __half g_WkT[(size_t)KVC * CDIM];
__device__ __align__(128) __half g_WvT[(size_t)KVC * CDIM];
__device__ __align__(128) __half g_WoT[(size_t)CDIM * CDIM];

__device__ __forceinline__ uint32_t smem_u32(const void* p) {
    uint32_t a;
    asm("{ .reg .u64 t; cvta.to.shared.u64 t, %1; cvt.u32.u64 %0, t; }"
        : "=r"(a) : "l"(p));
    return a;
}

#define MMA_F16(D, a0, a1, a2, a3, b0, b1)                                    \
    asm volatile(                                                             \
        "mma.sync.aligned.m16n8k16.row.col.f32.f16.f16.f32 "                  \
        "{%0,%1,%2,%3}, {%4,%5,%6,%7}, {%8,%9}, {%0,%1,%2,%3};"               \
        : "+f"(D[0]), "+f"(D[1]), "+f"(D[2]), "+f"(D[3])                      \
        : "r"(a0), "r"(a1), "r"(a2), "r"(a3), "r"(b0), "r"(b1))

#define CP_ASYNC16(saddr, gptr)                                               \
    asm volatile("cp.async.ca.shared.global [%0], [%1], 16;"                  \
                 :: "r"(saddr), "l"(gptr))
#define CP_COMMIT() asm volatile("cp.async.commit_group;" ::: "memory")
#define CP_WAIT0()  asm volatile("cp.async.wait_group 0;" ::: "memory")

// ---------------------------------------------------------------------------
// x -> half
// ---------------------------------------------------------------------------
__global__ __launch_bounds__(256)
void cvt_half(const float* __restrict__ in, __half* __restrict__ out, int n4)
{
    int i = blockIdx.x * 256 + threadIdx.x;
    if (i < n4) {
        float4 v = *(const float4*)(in + (size_t)i * 4);
        __half2* o = (__half2*)(out + (size_t)i * 4);
        o[0] = __floats2half2_rn(v.x, v.y);
        o[1] = __floats2half2_rn(v.z, v.w);
    }
}

// ---------------------------------------------------------------------------
// Weight transpose + half: Wt[n][k] = half(W[k][n])
// ---------------------------------------------------------------------------
__global__ __launch_bounds__(256)
void transpose_half(const float* __restrict__ W, __half* __restrict__ Wt,
                    int Kdim, int N)
{
    __shared__ float tile[32][33];
    const int bx = blockIdx.x * 32;   // n
    const int by = blockIdx.y * 32;   // k
    const int tx = threadIdx.x & 31;
    const int ty = threadIdx.x >> 5;
#pragma unroll
    for (int i = ty; i < 32; i += 8)
        tile[i][tx] = W[(size_t)(by + i) * N + bx + tx];
    __syncthreads();
#pragma unroll
    for (int i = ty; i < 32; i += 8)
        Wt[(size_t)(bx + i) * Kdim + by + tx] = __float2half_rn(tile[tx][i]);
}

// ---------------------------------------------------------------------------
// fp16 tensor-core GEMM: C[M,N] = A[M,K] @ Bt[N,K]^T  (A, Bt half, K-major)
// 128x128 tile, BK=32, 256 thr (8 warps: 4 m-groups x 2 n-groups),
// cp.async double-buffered smem. Padded stride 20 words/row (bank-safe).
// OUT_MODE: 0 = half [M][N], 1 = half transposed [N][M], 2 = float [M][N]
// ---------------------------------------------------------------------------
#define GW 20                      // words per smem tile row
#define GTILEW (128 * GW)          // words per tile

template <int OUT_MODE>
__global__ __launch_bounds__(256)
void gemm_h(const __half* __restrict__ A, const __half* __restrict__ Bt,
            void* __restrict__ Cv, int M, int N, int Kdim)
{
    __shared__ uint32_t sm[2 * 2 * GTILEW];   // [stage][A,B][tile]
    const uint32_t smb = smem_u32(sm);

    const int tid  = threadIdx.x;
    const int wid  = tid >> 5;
    const int lane = tid & 31;
    const int g = lane >> 2;
    const int t = lane & 3;
    const int wr = (wid & 3) * 32;
    const int wc = (wid >> 2) * 64;
    const int bm = blockIdx.y * 128;
    const int bn = blockIdx.x * 128;

    // load mapping: 2 chunks for A, 2 for B per thread per stage
    const int lrow = tid >> 1;                // 0..127
    const int lch0 = (tid & 1) * 2;           // chunk 0/2
    const __half* agp0 = A  + (size_t)(bm + lrow) * Kdim + lch0 * 8;
    const __half* bgp0 = Bt + (size_t)(bn + lrow) * Kdim + lch0 * 8;
    const uint32_t sa0 = smb + (uint32_t)(lrow * GW + lch0 * 4) * 4;

    float acc[2][8][4];
#pragma unroll
    for (int mt = 0; mt < 2; mt++)
#pragma unroll
        for (int nt = 0; nt < 8; nt++)
#pragma unroll
            for (int e = 0; e < 4; e++) acc[mt][nt][e] = 0.0f;

    const int NC = Kdim / 32;

    // preload chunk 0 into stage 0
    {
        const uint32_t sA = sa0;
        const uint32_t sB = sa0 + GTILEW * 4;
        CP_ASYNC16(sA,      agp0);
        CP_ASYNC16(sA + 16, agp0 + 8);
        CP_ASYNC16(sB,      bgp0);
        CP_ASYNC16(sB + 16, bgp0 + 8);
        CP_COMMIT();
    }

    for (int c = 0; c < NC; c++) {
        const int s = c & 1;
        CP_WAIT0();
        __syncthreads();

        if (c + 1 < NC) {
            const uint32_t sbase = sa0 + (uint32_t)((1 - s) * 2 * GTILEW) * 4;
            const __half* ag = agp0 + (c + 1) * 32;
            const __half* bg = bgp0 + (c + 1) * 32;
            CP_ASYNC16(sbase,                agp0 + (c + 1) * 32);
            CP_ASYNC16(sbase + 16,           ag + 8);
            CP_ASYNC16(sbase + GTILEW * 4,      bg);
            CP_ASYNC16(sbase + GTILEW * 4 + 16, bg + 8);
            CP_COMMIT();
        }

        const uint32_t* As = sm + s * 2 * GTILEW;
        const uint32_t* Bs = As + GTILEW;

#pragma unroll
        for (int ks = 0; ks < 2; ks++) {
            const int ko = 8 * ks + t;
            uint32_t a[2][4];
#pragma unroll
            for (int mt = 0; mt < 2; mt++) {
                int r0 = wr + mt * 16 + g;
                a[mt][0] = As[r0 * GW + ko];
                a[mt][1] = As[(r0 + 8) * GW + ko];
                a[mt][2] = As[r0 * GW + ko + 4];
                a[mt][3] = As[(r0 + 8) * GW + ko + 4];
            }
            uint32_t bf[8][2];
#pragma unroll
            for (int nt = 0; nt < 8; nt++) {
                int rn = wc + 8 * nt + g;
                bf[nt][0] = Bs[rn * GW + ko];
                bf[nt][1] = Bs[rn * GW + ko + 4];
            }
#pragma unroll
            for (int mt = 0; mt < 2; mt++)
#pragma unroll
                for (int nt = 0; nt < 8; nt++)
                    MMA_F16(acc[mt][nt], a[mt][0], a[mt][1], a[mt][2], a[mt][3],
                            bf[nt][0], bf[nt][1]);
        }
        __syncthreads();
    }

    // Epilogue
    if (OUT_MODE == 2) {
        float* C = (float*)Cv;
#pragma unroll
        for (int mt = 0; mt < 2; mt++) {
            int r = bm + wr + mt * 16 + g;
#pragma unroll
            for (int nt = 0; nt < 8; nt++) {
                int cc = bn + wc + 8 * nt + 2 * t;
                *(float2*)(C + (size_t)r * N + cc) =
                    make_float2(acc[mt][nt][0], acc[mt][nt][1]);
                *(float2*)(C + (size_t)(r + 8) * N + cc) =
                    make_float2(acc[mt][nt][2], acc[mt][nt][3]);
            }
        }
    } else if (OUT_MODE == 0) {
        __half2* C = (__half2*)Cv;
#pragma unroll
        for (int mt = 0; mt < 2; mt++) {
            int r = bm + wr + mt * 16 + g;
#pragma unroll
            for (int nt = 0; nt < 8; nt++) {
                int cw = (bn + wc + 8 * nt + 2 * t) >> 1;
                C[(size_t)r * (N >> 1) + cw] =
                    __floats2half2_rn(acc[mt][nt][0], acc[mt][nt][1]);
                C[(size_t)(r + 8) * (N >> 1) + cw] =
                    __floats2half2_rn(acc[mt][nt][2], acc[mt][nt][3]);
            }
        }
    } else {  // OUT_MODE == 1 : transposed half, C[N][M]
        __half* C = (__half*)Cv;
#pragma unroll
        for (int mt = 0; mt < 2; mt++) {
            int m0 = bm + wr + mt * 16 + g;
#pragma unroll
            for (int nt = 0; nt < 8; nt++) {
                int n0 = bn + wc + 8 * nt + 2 * t;
                C[(size_t)n0 * M + m0]           = __float2half_rn(acc[mt][nt][0]);
                C[(size_t)(n0 + 1) * M + m0]     = __float2half_rn(acc[mt][nt][1]);
                C[(size_t)n0 * M + m0 + 8]       = __float2half_rn(acc[mt][nt][2]);
                C[(size_t)(n0 + 1) * M + m0 + 8] = __float2half_rn(acc[mt][nt][3]);
            }
        }
    }
}

// ---------------------------------------------------------------------------
// fp16 flash attention, causal, GQA. 256 thr (8 warps x 16 rows = BQ 128).
// BKV=64. Smem word strides: Qs/Ks 68, Vt/Ps 36 (all ≡4 mod 32, bank-safe).
// ---------------------------------------------------------------------------
#define BQ 128
#define BKV 64
#define QW 68
#define KW 68
#define VW 36
#define PW 36

#define FLASH_SMEM_WORDS (BQ * QW + BKV * KW + HEADD * VW + BQ * PW)
#define FLASH_SMEM_BYTES (FLASH_SMEM_WORDS * 4)

__global__ __launch_bounds__(256, 1)
void flash_h(const __half* __restrict__ Q, const __half* __restrict__ K,
             const __half* __restrict__ Vt, __half* __restrict__ Y)
{
    extern __shared__ uint32_t fsm[];
    uint32_t* Qs = fsm;                   // BQ   x QW
    uint32_t* Ks = Qs + BQ * QW;          // BKV  x KW
    uint32_t* Vs = Ks + BKV * KW;         // HEADD x VW   (V^T tile)
    uint32_t* Ps = Vs + HEADD * VW;       // BQ   x PW

    const int q0  = blockIdx.x * BQ;
    const int h   = blockIdx.y;
    const int b   = blockIdx.z;
    const int kvh = h / GROUP;
    const int tid  = threadIdx.x;
    const int wid  = tid >> 5;
    const int lane = tid & 31;
    const int g = lane >> 2;
    const int t = lane & 3;
    const int wr = wid * 16;
    const float scale = 0.08838834764831845f;   // 1/sqrt(128)

    // Load Q tile: 128 rows x 128 halves (16 uint4 chunks per row)
    const __half* Qbase = Q + (size_t)(b * SEQ + q0) * CDIM + h * HEADD;
#pragma unroll
    for (int i = 0; i < 8; i++) {
        int slot = tid + i * 256;         // 0..2047
        int r = slot >> 4, ch = slot & 15;
        *(uint4*)(Qs + r * QW + ch * 4) =
            *(const uint4*)(Qbase + (size_t)r * CDIM + ch * 8);
    }

    float oa[16][4];
#pragma unroll
    for (int nt = 0; nt < 16; nt++)
#pragma unroll
        for (int e = 0; e < 4; e++) oa[nt][e] = 0.0f;
    float m0 = -1e30f, m1 = -1e30f, l0 = 0.0f, l1 = 0.0f;

    const int qrow0 = q0 + wr + g;
    const int qrow1 = qrow0 + 8;
    const int ntiles = q0 / BKV + 2;

    for (int tt = 0; tt < ntiles; tt++) {
        const int k0 = tt * BKV;
        __syncthreads();

        const __half* Kbase  = K  + (size_t)(b * SEQ + k0) * KVC + kvh * HEADD;
        const __half* Vtbase = Vt + (size_t)(kvh * HEADD) * ROWS + b * SEQ + k0;
#pragma unroll
        for (int i = 0; i < 4; i++) {
            int slot = tid + i * 256;     // 0..1023
            int rk = slot >> 4, chk = slot & 15;
            *(uint4*)(Ks + rk * KW + chk * 4) =
                *(const uint4*)(Kbase + (size_t)rk * KVC + chk * 8);
            int rv = slot >> 3, chv = slot & 7;
            *(uint4*)(Vs + rv * VW + chv * 4) =
                *(const uint4*)(Vtbase + (size_t)rv * ROWS + chv * 8);
        }
        __syncthreads();

        // ---- S = Q @ K^T (warp: 16 x 64), 8 k16-steps over D=128 ----
        float sa[8][4];
#pragma unroll
        for (int j = 0; j < 8; j++)
#pragma unroll
            for (int e = 0; e < 4; e++) sa[j][e] = 0.0f;

#pragma unroll
        for (int ks = 0; ks < 8; ks++) {
            const int ko = 8 * ks + t;
            uint32_t a0 = Qs[(wr + g) * QW + ko];
            uint32_t a1 = Qs[(wr + 8 + g) * QW + ko];
            uint32_t a2 = Qs[(wr + g) * QW + ko + 4];
            uint32_t a3 = Qs[(wr + 8 + g) * QW + ko + 4];
#pragma unroll
            for (int j = 0; j < 8; j++) {
                uint32_t b0 = Ks[(8 * j + g) * KW + ko];
                uint32_t b1 = Ks[(8 * j + g) * KW + ko + 4];
                MMA_F16(sa[j], a0, a1, a2, a3, b0, b1);
            }
        }

        // ---- scale + causal mask + online softmax ----
        float ml0 = -1e30f, ml1 = -1e30f;
#pragma unroll
        for (int j = 0; j < 8; j++)
#pragma unroll
            for (int e = 0; e < 2; e++) {
                int key = k0 + 8 * j + 2 * t + e;
                float x0 = sa[j][e] * scale;
                float x1 = sa[j][2 + e] * scale;
                if (key > qrow0) x0 = -1e30f;
                if (key > qrow1) x1 = -1e30f;
                sa[j][e] = x0; sa[j][2 + e] = x1;
                ml0 = fmaxf(ml0, x0);
                ml1 = fmaxf(ml1, x1);
            }
        ml0 = fmaxf(ml0, __shfl_xor_sync(0xffffffffu, ml0, 1));
        ml0 = fmaxf(ml0, __shfl_xor_sync(0xffffffffu, ml0, 2));
        ml1 = fmaxf(ml1, __shfl_xor_sync(0xffffffffu, ml1, 1));
        ml1 = fmaxf(ml1, __shfl_xor_sync(0xffffffffu, ml1, 2));

        float mn0 = fmaxf(m0, ml0), mn1 = fmaxf(m1, ml1);
        float corr0 = __expf(m0 - mn0), corr1 = __expf(m1 - mn1);
        m0 = mn0; m1 = mn1;

        float s0 = 0.0f, s1 = 0.0f;
#pragma unroll
        for (int j = 0; j < 8; j++) {
            float p00 = __expf(sa[j][0] - mn0);
            float p01 = __expf(sa[j][1] - mn0);
            float p10 = __expf(sa[j][2] - mn1);
            float p11 = __expf(sa[j][3] - mn1);
            s0 += p00 + p01;
            s1 += p10 + p11;
            Ps[(wr + g) * PW + 4 * j + t]     = __float_as_uint(0.0f),
            ((__half2*)Ps)[(wr + g) * PW + 4 * j + t]     = __floats2half2_rn(p00, p01);
            ((__half2*)Ps)[(wr + 8 + g) * PW + 4 * j + t] = __floats2half2_rn(p10, p11);
        }
        s0 += __shfl_xor_sync(0xffffffffu, s0, 1);
        s0 += __shfl_xor_sync(0xffffffffu, s0, 2);
        s1 += __shfl_xor_sync(0xffffffffu, s1, 1);
        s1 += __shfl_xor_sync(0xffffffffu, s1, 2);
        l0 = l0 * corr0 + s0;
        l1 = l1 * corr1 + s1;

#pragma unroll
        for (int nt = 0; nt < 16; nt++) {
            oa[nt][0] *= corr0; oa[nt][1] *= corr0;
            oa[nt][2] *= corr1; oa[nt][3] *= corr1;
        }
        __syncwarp();

        // ---- O += P @ V (warp: 16 x 128), 4 k16-steps over BKV ----
#pragma unroll
        for (int ks = 0; ks < 4; ks++) {
            const int ko = 8 * ks + t;
            uint32_t a0 = Ps[(wr + g) * PW + ko];
            uint32_t a1 = Ps[(wr + 8 + g) * PW + ko];
            uint32_t a2 = Ps[(wr + g) * PW + ko + 4];
            uint32_t a3 = Ps[(wr + 8 + g) * PW + ko + 4];
#pragma unroll
            for (int nt = 0; nt < 16; nt++) {
                uint32_t b0 = Vs[(8 * nt + g) * VW + ko];
                uint32_t b1 = Vs[(8 * nt + g) * VW + ko + 4];
                MMA_F16(oa[nt], a0, a1, a2, a3, b0, b1);
            }
        }
    }

    // ---- normalize + write Y (half) in (B,T,H,D) layout ----
    const float inv0 = 1.0f / l0, inv1 = 1.0f / l1;
    __half2* Yb = (__half2*)(Y + (size_t)(b * SEQ + q0 + wr) * CDIM + h * HEADD);
    const int wstr = CDIM >> 1;
#pragma unroll
    for (int nt = 0; nt < 16; nt++) {
        int cw = 4 * nt + t;
        Yb[(size_t)g * wstr + cw] =
            __floats2half2_rn(oa[nt][0] * inv0, oa[nt][1] * inv0);
        Yb[(size_t)(g + 8) * wstr + cw] =
            __floats2half2_rn(oa[nt][2] * inv1, oa[nt][3] * inv1);
    }
}

// ---------------------------------------------------------------------------
extern "C" void kernel_launch(void* const* d_in, const int* in_sizes, int n_in,
                              void* d_out, int out_size)
{
    const float* x  = (const float*)d_in[0];
    const float* Wq = (const float*)d_in[1];
    const float* Wk = (const float*)d_in[2];
    const float* Wv = (const float*)d_in[3];
    const float* Wo = (const float*)d_in[4];
    float* out = (float*)d_out;

    __half *xh, *Qh, *Kh, *Vt, *Yh, *WqT, *WkT, *WvT, *WoT;
    cudaGetSymbolAddress((void**)&xh,  g_xh);
    cudaGetSymbolAddress((void**)&Qh,  g_Qh);
    cudaGetSymbolAddress((void**)&Kh,  g_Kh);
    cudaGetSymbolAddress((void**)&Vt,  g_Vt);
    cudaGetSymbolAddress((void**)&Yh,  g_Yh);
    cudaGetSymbolAddress((void**)&WqT, g_WqT);
    cudaGetSymbolAddress((void**)&WkT, g_WkT);
    cudaGetSymbolAddress((void**)&WvT, g_WvT);
    cudaGetSymbolAddress((void**)&WoT, g_WoT);

    // Pre-pass: x -> half; weights -> transposed half (K-major B operands)
    cvt_half<<<(ROWS * CDIM / 4 + 255) / 256, 256>>>(x, xh, ROWS * CDIM / 4);
    transpose_half<<<dim3(CDIM / 32, CDIM / 32), 256>>>(Wq, WqT, CDIM, CDIM);
    transpose_half<<<dim3(KVC  / 32, CDIM / 32), 256>>>(Wk, WkT, CDIM, KVC);
    transpose_half<<<dim3(KVC  / 32, CDIM / 32), 256>>>(Wv, WvT, CDIM, KVC);
    transpose_half<<<dim3(CDIM / 32, CDIM / 32), 256>>>(Wo, WoT, CDIM, CDIM);

    // QKV projections (fp16 mma)
    gemm_h<0><<<dim3(CDIM / 128, ROWS / 128), 256>>>(xh, WqT, Qh, ROWS, CDIM, CDIM);
    gemm_h<0><<<dim3(KVC / 128, ROWS / 128), 256>>>(xh, WkT, Kh, ROWS, KVC, CDIM);
    gemm_h<1><<<dim3(KVC / 128, ROWS / 128), 256>>>(xh, WvT, Vt, ROWS, KVC, CDIM);

    // Flash attention (fp16 mma)
    cudaFuncSetAttribute(flash_h, cudaFuncAttributeMaxDynamicSharedMemorySize,
                         FLASH_SMEM_BYTES);
    flash_h<<<dim3(SEQ / BQ, NHEAD, BATCH), 256, FLASH_SMEM_BYTES>>>(
        Qh, Kh, Vt, Yh);

    // Output projection (fp32 out)
    gemm_h<2><<<dim3(CDIM / 128, ROWS / 128), 256>>>(Yh, WoT, out, ROWS, CDIM, CDIM);
}